// round 15
// baseline (speedup 1.0000x reference)
#include <cuda_runtime.h>
#include <math.h>
#include <stdint.h>

#define NV 32768
#define EV 512
#define DV 32
#define CV 50
#define H3V 281
#define H3P 320          // padded fc3 width (multiple of 64)
#define LDL 64           // padded logits width (>= CV, multiple of 64)
#define FULLM 0xffffffffu

// ---------------- device scratch (static, no allocation) ----------------
__device__ float g_bufA[NV * EV];
__device__ float g_bufB[NV * EV];
__device__ float g_logits[NV * LDL];
__device__ float g_gumbel[NV * CV];
__device__ float g_terms[NV];
__device__ int   g_colors[NV];
__device__ int   g_pos[NV];
__device__ int   g_viol;
__device__ int   g_next;
// transposed + tf32-split + padded weights: [Np][Kp]
__device__ float g_W1h[EV * EV],  g_W1l[EV * EV];
__device__ float g_W2h[EV * EV],  g_W2l[EV * EV];
__device__ float g_W3h[H3P * EV], g_W3l[H3P * EV];
__device__ float g_W4h[LDL * H3P], g_W4l[LDL * H3P];
__device__ float g_b3p[H3P];
__device__ float g_b4p[LDL];

// ---------------- helpers ----------------
__device__ __forceinline__ unsigned fenc(float f) {
    unsigned u = __float_as_uint(f);
    return (u & 0x80000000u) ? ~u : (u | 0x80000000u);
}
__device__ __forceinline__ float fdec(unsigned u) {
    return (u & 0x80000000u) ? __uint_as_float(u ^ 0x80000000u)
                             : __uint_as_float(~u);
}
__device__ __forceinline__ unsigned rotl32(unsigned x, int r) {
    return (x << r) | (x >> (32 - r));
}
__device__ __forceinline__ float tf32_rn(float a) {
    unsigned r;
    asm("cvt.rna.tf32.f32 %0, %1;" : "=r"(r) : "f"(a));
    return __uint_as_float(r);
}

#define MMA_TF32(d, a, b) \
    asm volatile("mma.sync.aligned.m16n8k8.row.col.f32.tf32.tf32.f32 " \
        "{%0,%1,%2,%3}, {%4,%5,%6,%7}, {%8,%9}, {%0,%1,%2,%3};" \
        : "+f"((d)[0]), "+f"((d)[1]), "+f"((d)[2]), "+f"((d)[3]) \
        : "r"((a)[0]), "r"((a)[1]), "r"((a)[2]), "r"((a)[3]), \
          "r"((b)[0]), "r"((b)[1]))

#define CPA16(dst, src) \
    asm volatile("cp.async.cg.shared.global [%0], [%1], 16;" \
                 :: "r"(dst), "l"(src) : "memory")
#define CP_COMMIT  asm volatile("cp.async.commit_group;" ::: "memory")
#define CP_WAIT(n) asm volatile("cp.async.wait_group %0;" :: "n"(n) : "memory")

// ---------------- fused weight prep (ONE launch) -------------------------
#define PW1_END  (EV * EV)
#define PW2_END  (2 * EV * EV)
#define PW3_END  (2 * EV * EV + H3P * EV)
#define PW4_END  (2 * EV * EV + H3P * EV + LDL * H3P)
#define PB3_END  (PW4_END + H3P)
#define PB4_END  (PB3_END + LDL)

__global__ void prep_all_kernel(const float* __restrict__ W1,
                                const float* __restrict__ W2,
                                const float* __restrict__ W3,
                                const float* __restrict__ W4,
                                const float* __restrict__ b3,
                                const float* __restrict__ b4)
{
    int gi = blockIdx.x * blockDim.x + threadIdx.x;
    if (gi < PW2_END) {
        const float* W; float *Wh, *Wl; int idx;
        if (gi < PW1_END) { W = W1; Wh = g_W1h; Wl = g_W1l; idx = gi; }
        else              { W = W2; Wh = g_W2h; Wl = g_W2l; idx = gi - PW1_END; }
        int n = idx / EV, k = idx % EV;
        float w = W[(size_t)k * EV + n];
        float hi = tf32_rn(w);
        Wh[idx] = hi; Wl[idx] = tf32_rn(w - hi);
    } else if (gi < PW3_END) {
        int idx = gi - PW2_END;
        int n = idx / EV, k = idx % EV;
        float w = (n < H3V) ? W3[(size_t)k * H3V + n] : 0.f;
        float hi = tf32_rn(w);
        g_W3h[idx] = hi; g_W3l[idx] = tf32_rn(w - hi);
    } else if (gi < PW4_END) {
        int idx = gi - PW3_END;
        int n = idx / H3P, k = idx % H3P;
        float w = (n < CV && k < H3V) ? W4[(size_t)k * CV + n] : 0.f;
        float hi = tf32_rn(w);
        g_W4h[idx] = hi; g_W4l[idx] = tf32_rn(w - hi);
    } else if (gi < PB3_END) {
        int i = gi - PW4_END;
        g_b3p[i] = (i < H3V) ? b3[i] : 0.f;
    } else if (gi < PB4_END) {
        int i = gi - PB3_END;
        g_b4p[i] = (i < CV) ? b4[i] : 0.f;
    }
}

// ---------------- 3xTF32 mma.sync GEMM (BN=64, 3 CTAs/SM) ----------------
// BM=128, BN=64. Two-sync cp.async double buffer (measured best). 8 warps
// as 32x32 tiles: wm = wid&3 (32-row band), wn = wid>>2 (32-col half).
// Inner loop nt-outer so only one B fragment pair is live => ~70 live regs,
// fits the 85-reg cap for 3 CTAs/SM (3 x 73.7KB = 221KB smem).
// Per-element accumulation order (k asc, LH/HL/HH) UNCHANGED => bit-exact.
#define GSTRIDE 36
#define BN64    64
#define A_F     (128 * GSTRIDE)
#define B_F     (BN64 * GSTRIDE)
#define STG_F   (A_F + 2 * B_F)
#define OFF_A   0
#define OFF_BH  A_F
#define OFF_BL  (A_F + B_F)
#define GT_SMEM (2 * STG_F * 4)            // 73728 bytes

__global__ void __launch_bounds__(256, 3) gemm_tc_kernel(
    const float* __restrict__ A, const float* __restrict__ Bh,
    const float* __restrict__ Bl, const float* __restrict__ bias,
    float* __restrict__ C, int Kp, int Np, int lda, int ldc, int act)
{
    extern __shared__ float sm[];
    const int tid  = threadIdx.x;
    const int wid  = tid >> 5;
    const int lane = tid & 31;
    const int lr   = lane >> 2;       // 0..7
    const int lc   = lane & 3;        // 0..3
    const int wm   = wid & 3;         // 32-row band (0..3)
    const int wn   = wid >> 2;        // 32-col half (0..1)
    const int rowBase = blockIdx.y * 128;
    const int colBase = blockIdx.x * BN64;
    const uint32_t sbase = (uint32_t)__cvta_generic_to_shared(sm);

    const int r0 = tid >> 3;          // 0..31
    const int q0 = tid & 7;           // 0..7

    float acc[2][4][4];
#pragma unroll
    for (int mt = 0; mt < 2; mt++)
#pragma unroll
        for (int nt = 0; nt < 4; nt++)
#pragma unroll
            for (int q = 0; q < 4; q++) acc[mt][nt][q] = 0.f;

    const int nchunks = Kp / 32;

#define STAGE(s, kb) do {                                                     \
        uint32_t sb_ = sbase + (s) * (STG_F * 4);                             \
        _Pragma("unroll")                                                     \
        for (int i_ = 0; i_ < 4; i_++) {                                      \
            int r_ = r0 + 32 * i_;                                            \
            uint32_t so_ = (uint32_t)((r_ * GSTRIDE + 4 * q0) * 4);           \
            CPA16(sb_ + OFF_A * 4 + so_,                                      \
                  A + (size_t)(rowBase + r_) * lda + (kb) + 4 * q0);          \
        }                                                                     \
        _Pragma("unroll")                                                     \
        for (int i_ = 0; i_ < 2; i_++) {                                      \
            int r_ = r0 + 32 * i_;                                            \
            uint32_t so_ = (uint32_t)((r_ * GSTRIDE + 4 * q0) * 4);           \
            CPA16(sb_ + OFF_BH * 4 + so_,                                     \
                  Bh + (size_t)(colBase + r_) * Kp + (kb) + 4 * q0);          \
            CPA16(sb_ + OFF_BL * 4 + so_,                                     \
                  Bl + (size_t)(colBase + r_) * Kp + (kb) + 4 * q0);          \
        }                                                                     \
        CP_COMMIT;                                                            \
    } while (0)

    STAGE(0, 0);

    for (int ch = 0; ch < nchunks; ch++) {
        if (ch + 1 < nchunks) {
            STAGE((ch + 1) & 1, (ch + 1) * 32);
            CP_WAIT(1);
        } else {
            CP_WAIT(0);
        }
        __syncthreads();

        const float* sA  = sm + (ch & 1) * STG_F + OFF_A;
        const float* sBH = sm + (ch & 1) * STG_F + OFF_BH;
        const float* sBL = sm + (ch & 1) * STG_F + OFF_BL;

#pragma unroll
        for (int ks = 0; ks < 4; ks++) {
            const int k0 = ks * 8;
            unsigned aH[2][4], aL[2][4];
#pragma unroll
            for (int mt = 0; mt < 2; mt++) {
                int base = (wm * 32 + mt * 16 + lr) * GSTRIDE + k0 + lc;
                float r0v = sA[base];
                float r1v = sA[base + 8 * GSTRIDE];
                float r2v = sA[base + 4];
                float r3v = sA[base + 8 * GSTRIDE + 4];
                float h0 = tf32_rn(r0v), h1 = tf32_rn(r1v);
                float h2 = tf32_rn(r2v), h3 = tf32_rn(r3v);
                aH[mt][0] = __float_as_uint(h0);
                aH[mt][1] = __float_as_uint(h1);
                aH[mt][2] = __float_as_uint(h2);
                aH[mt][3] = __float_as_uint(h3);
                aL[mt][0] = __float_as_uint(tf32_rn(r0v - h0));
                aL[mt][1] = __float_as_uint(tf32_rn(r1v - h1));
                aL[mt][2] = __float_as_uint(tf32_rn(r2v - h2));
                aL[mt][3] = __float_as_uint(tf32_rn(r3v - h3));
            }
#pragma unroll
            for (int nt = 0; nt < 4; nt++) {
                int base = (wn * 32 + nt * 8 + lr) * GSTRIDE + k0 + lc;
                unsigned bh[2], bl[2];
                bh[0] = __float_as_uint(sBH[base]);
                bh[1] = __float_as_uint(sBH[base + 4]);
                bl[0] = __float_as_uint(sBL[base]);
                bl[1] = __float_as_uint(sBL[base + 4]);
#pragma unroll
                for (int mt = 0; mt < 2; mt++) {
                    MMA_TF32(acc[mt][nt], aL[mt], bh);
                    MMA_TF32(acc[mt][nt], aH[mt], bl);
                    MMA_TF32(acc[mt][nt], aH[mt], bh);
                }
            }
        }
        __syncthreads();
    }
#undef STAGE

    // epilogue: bias + leaky + store
#pragma unroll
    for (int mt = 0; mt < 2; mt++) {
        int row = rowBase + wm * 32 + mt * 16 + lr;
#pragma unroll
        for (int nt = 0; nt < 4; nt++) {
            int col = colBase + wn * 32 + nt * 8 + lc * 2;
            float v0 = acc[mt][nt][0] + bias[col];
            float v1 = acc[mt][nt][1] + bias[col + 1];
            float v2 = acc[mt][nt][2] + bias[col];
            float v3 = acc[mt][nt][3] + bias[col + 1];
            if (act) {
                v0 = (v0 >= 0.f) ? v0 : 0.01f * v0;
                v1 = (v1 >= 0.f) ? v1 : 0.01f * v1;
                v2 = (v2 >= 0.f) ? v2 : 0.01f * v2;
                v3 = (v3 >= 0.f) ? v3 : 0.01f * v3;
            }
            C[(size_t)row * ldc + col]           = v0;
            C[(size_t)row * ldc + col + 1]       = v1;
            C[(size_t)(row + 8) * ldc + col]     = v2;
            C[(size_t)(row + 8) * ldc + col + 1] = v3;
        }
    }
}

// ---------------- fused gumbel + pos/init (ONE launch) -------------------
__global__ void gumbel_pos_kernel(const int* __restrict__ vorder)
{
    const int total = (NV - 1) * CV;
    int i = blockIdx.x * blockDim.x + threadIdx.x;
    if (i < NV) {
        g_pos[vorder[i]] = i;
        g_colors[i] = -1;
    }
    if (i == 0) { g_viol = 0; g_next = 1; }
    if (i >= total) return;
    unsigned x0 = 0u;
    unsigned x1 = (unsigned)i;
    const unsigned k0 = 0u, k1 = 42u, k2 = 0u ^ 42u ^ 0x1BD11BDAu;
    x0 += k0; x1 += k1;
#define TFR(r) { x0 += x1; x1 = rotl32(x1, r); x1 ^= x0; }
    TFR(13) TFR(15) TFR(26) TFR(6)  x0 += k1; x1 += k2 + 1u;
    TFR(17) TFR(29) TFR(16) TFR(24) x0 += k2; x1 += k0 + 2u;
    TFR(13) TFR(15) TFR(26) TFR(6)  x0 += k0; x1 += k1 + 3u;
    TFR(17) TFR(29) TFR(16) TFR(24) x0 += k1; x1 += k2 + 4u;
    TFR(13) TFR(15) TFR(26) TFR(6)  x0 += k2; x1 += k0 + 5u;
#undef TFR
    unsigned bits = x0 ^ x1;
    unsigned fb = (bits >> 9) | 0x3f800000u;
    float f = __uint_as_float(fb) - 1.0f;
    const float tiny = 1.17549435e-38f;
    float u = fmaxf(tiny, f + tiny);
    g_gumbel[i] = -logf(-logf(u));
}

// ---------------- wavefront dataflow scan (dynamic assignment) -----------
#define SCAN_BLOCKS 296
#define SCAN_TPB    512

__global__ void __launch_bounds__(SCAN_TPB, 2) wavescan_kernel(
    const int* __restrict__ vorder, const int* __restrict__ adj)
{
    const int lane = threadIdx.x & 31;
    volatile int* vcol = g_colors;

    if (blockIdx.x == 0 && threadIdx.x == 0) {
        vcol[vorder[0]] = 0;               // first vertex -> color 0
    }

    const int c1 = lane + 32;
    const bool ok1 = (c1 < CV);
    const float NEGINF = __int_as_float((int)0xff800000);

    for (;;) {
        int t;
        if (lane == 0) t = atomicAdd(&g_next, 1);
        t = __shfl_sync(FULLM, t, 0);
        if (t >= NV) break;

        int v  = vorder[t];
        int nb = adj[v * DV + lane];
        int pn = g_pos[nb];
        float l0 = g_logits[v * LDL + lane];
        float l1 = ok1 ? g_logits[v * LDL + c1] : 0.f;
        float g0 = g_gumbel[(t - 1) * CV + lane];
        float g1 = ok1 ? g_gumbel[(t - 1) * CV + c1] : 0.f;

        bool need = (pn < t);
        int cn = -1;
        while (__any_sync(FULLM, need && cn < 0)) {
            if (need && cn < 0) cn = vcol[nb];
        }

        unsigned lo = 0u, hi = 0u;
        if (need) {
            if (cn < 32) lo = 1u << cn; else hi = 1u << (cn - 32);
        }
        lo = __reduce_or_sync(FULLM, lo);
        hi = __reduce_or_sync(FULLM, hi);

        bool m0 = (lo >> lane) & 1u;
        bool m1 = (!ok1) || ((hi >> lane) & 1u);
        float s0 = m0 ? NEGINF : (l0 + g0);
        float s1 = m1 ? NEGINF : (l1 + g1);
        float s; int idx;
        if (s1 > s0) { s = s1; idx = c1; } else { s = s0; idx = lane; }
        unsigned e = fenc(s);
        unsigned m = __reduce_max_sync(FULLM, e);
        unsigned ic = (e == m) ? (unsigned)idx : 64u;
        int chosen = (int)__reduce_min_sync(FULLM, ic);

        if (lane == 0) vcol[v] = chosen;   // publish ASAP

        // ---- logp term (off critical path) ----
        float mx = fmaxf(m0 ? NEGINF : l0, m1 ? NEGINF : l1);
        mx = fdec(__reduce_max_sync(FULLM, fenc(mx)));
        float ex = (m0 ? 0.f : expf(l0 - mx)) + (m1 ? 0.f : expf(l1 - mx));
#pragma unroll
        for (int o = 16; o; o >>= 1) ex += __shfl_xor_sync(FULLM, ex, o);
        float la = __shfl_sync(FULLM, l0, chosen & 31);
        float lb = __shfl_sync(FULLM, l1, chosen & 31);
        if (lane == 0) {
            float lc = (chosen < 32) ? la : lb;
            float prob = expf(lc - mx) / ex;
            g_terms[t] = logf(prob + 1e-8f) + 18.420680743952367f;
        }
    }
}

// ---------------- fused violation count + colors output ------------------
__global__ void viol_out_kernel(const int* __restrict__ adj,
                                float* __restrict__ out, int do_colors)
{
    int i = blockIdx.x * blockDim.x + threadIdx.x;
    int c = 0;
    if (i < NV * DV) {
        int n = i >> 5;            // DV == 32
        c = (g_colors[adj[i]] == g_colors[n]) ? 1 : 0;
    }
    c = __reduce_add_sync(FULLM, c);
    if ((threadIdx.x & 31) == 0 && c) atomicAdd(&g_viol, c);
    if (do_colors && i < NV) out[i] = (float)g_colors[i];
}

// ---------------- final reduction ----------------
__global__ void final_kernel(float* out, int mode)
{
    const int tid = threadIdx.x;
    float s = 0.f;
    for (int t = 1 + tid; t < NV; t += 1024) s += g_terms[t];
    unsigned long long um = 0ull;
    for (int i = tid; i < NV; i += 1024) um |= (1ull << (g_colors[i] & 63));
#pragma unroll
    for (int o = 16; o; o >>= 1) {
        s  += __shfl_xor_sync(FULLM, s, o);
        um |= __shfl_xor_sync(FULLM, um, o);
    }
    __shared__ float ws[32];
    __shared__ unsigned long long wm[32];
    int w = tid >> 5, l = tid & 31;
    if (l == 0) { ws[w] = s; wm[w] = um; }
    __syncthreads();
    if (tid == 0) {
        float tot = 0.f; unsigned long long m = 0ull;
        for (int i = 0; i < 32; i++) { tot += ws[i]; m |= wm[i]; }
        float confidence = tot / (float)NV;
        int nused = __popcll(m);
        float ratio = (float)g_viol / (float)(NV * DV);
        float cost = (float)nused + ratio * 100.0f;
        float loss = cost * confidence;
        if (mode == 0) out[NV] = loss;
        else           out[0]  = loss;
    }
}

// ---------------- host ----------------
extern "C" void kernel_launch(void* const* d_in, const int* in_sizes, int n_in,
                              void* d_out, int out_size)
{
    const float *emb = 0, *W1 = 0, *b1 = 0, *W2 = 0, *b2 = 0,
                *W3 = 0, *b3 = 0, *W4 = 0, *b4 = 0;
    const int *adj = 0, *vorder = 0;
    for (int i = 0; i < n_in; i++) {
        long s = in_sizes[i];
        void* p = d_in[i];
        if      (s == (long)NV * EV)  emb = (const float*)p;
        else if (s == (long)NV * DV)  adj = (const int*)p;
        else if (s == NV)             vorder = (const int*)p;
        else if (s == (long)EV * EV)  { if (!W1) W1 = (const float*)p; else W2 = (const float*)p; }
        else if (s == EV)             { if (!b1) b1 = (const float*)p; else b2 = (const float*)p; }
        else if (s == (long)EV * H3V) W3 = (const float*)p;
        else if (s == H3V)            b3 = (const float*)p;
        else if (s == (long)H3V * CV) W4 = (const float*)p;
        else if (s == CV)             b4 = (const float*)p;
    }
    if (!emb || !adj || !vorder || !W1 || !b1 || !W2 || !b2 || !W3 || !b3 || !W4 || !b4)
        return;

    float *h1, *h2, *logits;
    float *w1h, *w1l, *w2h, *w2l, *w3h, *w3l, *w4h, *w4l, *b3p, *b4p;
    cudaGetSymbolAddress((void**)&h1, g_bufA);
    cudaGetSymbolAddress((void**)&h2, g_bufB);
    cudaGetSymbolAddress((void**)&logits, g_logits);
    cudaGetSymbolAddress((void**)&w1h, g_W1h); cudaGetSymbolAddress((void**)&w1l, g_W1l);
    cudaGetSymbolAddress((void**)&w2h, g_W2h); cudaGetSymbolAddress((void**)&w2l, g_W2l);
    cudaGetSymbolAddress((void**)&w3h, g_W3h); cudaGetSymbolAddress((void**)&w3l, g_W3l);
    cudaGetSymbolAddress((void**)&w4h, g_W4h); cudaGetSymbolAddress((void**)&w4l, g_W4l);
    cudaGetSymbolAddress((void**)&b3p, g_b3p); cudaGetSymbolAddress((void**)&b4p, g_b4p);

    cudaFuncSetAttribute(gemm_tc_kernel,
                         cudaFuncAttributeMaxDynamicSharedMemorySize, GT_SMEM);

    // fused weight prep (launch index 0)
    prep_all_kernel<<<(PB4_END + 255) / 256, 256>>>(W1, W2, W3, W4, b3, b4);

    // MLP GEMMs, all BN=64 with 3 CTAs/SM (index 3 = gemm3 gets profiled)
    gemm_tc_kernel<<<dim3(EV / 64, NV / 128), 256, GT_SMEM>>>(
        emb, w1h, w1l, b1, h1, EV, EV, EV, EV, 1);
    gemm_tc_kernel<<<dim3(EV / 64, NV / 128), 256, GT_SMEM>>>(
        h1, w2h, w2l, b2, h2, EV, EV, EV, EV, 1);
    gemm_tc_kernel<<<dim3(H3P / 64, NV / 128), 256, GT_SMEM>>>(
        h2, w3h, w3l, b3p, h1, EV, H3P, EV, H3P, 1);
    gemm_tc_kernel<<<dim3(LDL / 64, NV / 128), 256, GT_SMEM>>>(
        h1, w4h, w4l, b4p, logits, H3P, LDL, H3P, LDL, 0);

    gumbel_pos_kernel<<<((NV - 1) * CV + 255) / 256, 256>>>(vorder);

    wavescan_kernel<<<SCAN_BLOCKS, SCAN_TPB>>>(vorder, adj);

    float* outF = (float*)d_out;
    int do_colors = (out_size >= NV) ? 1 : 0;
    viol_out_kernel<<<(NV * DV + 255) / 256, 256>>>(adj, outF, do_colors);

    int mode = (out_size >= NV + 1) ? 0 : ((out_size < NV) ? 1 : 2);
    if (mode != 2)
        final_kernel<<<1, 1024>>>(outF, mode);
}

// round 16
// speedup vs baseline: 1.0835x; 1.0835x over previous
#include <cuda_runtime.h>
#include <math.h>
#include <stdint.h>

#define NV 32768
#define EV 512
#define DV 32
#define CV 50
#define H3V 281
#define H3P 320          // padded fc3 width (multiple of 64)
#define LDL 64           // padded logits width (>= CV, multiple of 64)
#define FULLM 0xffffffffu

// ---------------- device scratch (static, no allocation) ----------------
__device__ float g_bufA[NV * EV];
__device__ float g_bufB[NV * EV];
__device__ float g_logits[NV * LDL];
__device__ float g_gumbel[NV * CV];
__device__ float g_terms[NV];
__device__ int   g_colors[NV];
__device__ int   g_pos[NV];
__device__ int   g_viol;
__device__ int   g_next;
// transposed + tf32-split + padded weights: [Np][Kp]
__device__ float g_W1h[EV * EV],  g_W1l[EV * EV];
__device__ float g_W2h[EV * EV],  g_W2l[EV * EV];
__device__ float g_W3h[H3P * EV], g_W3l[H3P * EV];
__device__ float g_W4h[LDL * H3P], g_W4l[LDL * H3P];
__device__ float g_b3p[H3P];
__device__ float g_b4p[LDL];

// ---------------- helpers ----------------
__device__ __forceinline__ unsigned fenc(float f) {
    unsigned u = __float_as_uint(f);
    return (u & 0x80000000u) ? ~u : (u | 0x80000000u);
}
__device__ __forceinline__ float fdec(unsigned u) {
    return (u & 0x80000000u) ? __uint_as_float(u ^ 0x80000000u)
                             : __uint_as_float(~u);
}
__device__ __forceinline__ unsigned rotl32(unsigned x, int r) {
    return (x << r) | (x >> (32 - r));
}
__device__ __forceinline__ float tf32_rn(float a) {
    unsigned r;
    asm("cvt.rna.tf32.f32 %0, %1;" : "=r"(r) : "f"(a));
    return __uint_as_float(r);
}

#define MMA_TF32(d, a, b) \
    asm volatile("mma.sync.aligned.m16n8k8.row.col.f32.tf32.tf32.f32 " \
        "{%0,%1,%2,%3}, {%4,%5,%6,%7}, {%8,%9}, {%0,%1,%2,%3};" \
        : "+f"((d)[0]), "+f"((d)[1]), "+f"((d)[2]), "+f"((d)[3]) \
        : "r"((a)[0]), "r"((a)[1]), "r"((a)[2]), "r"((a)[3]), \
          "r"((b)[0]), "r"((b)[1]))

#define CPA16(dst, src) \
    asm volatile("cp.async.cg.shared.global [%0], [%1], 16;" \
                 :: "r"(dst), "l"(src) : "memory")
#define CP_COMMIT  asm volatile("cp.async.commit_group;" ::: "memory")
#define CP_WAIT(n) asm volatile("cp.async.wait_group %0;" :: "n"(n) : "memory")

// ---------------- fused weight prep (ONE launch) -------------------------
#define PW1_END  (EV * EV)
#define PW2_END  (2 * EV * EV)
#define PW3_END  (2 * EV * EV + H3P * EV)
#define PW4_END  (2 * EV * EV + H3P * EV + LDL * H3P)
#define PB3_END  (PW4_END + H3P)
#define PB4_END  (PB3_END + LDL)

__global__ void prep_all_kernel(const float* __restrict__ W1,
                                const float* __restrict__ W2,
                                const float* __restrict__ W3,
                                const float* __restrict__ W4,
                                const float* __restrict__ b3,
                                const float* __restrict__ b4)
{
    int gi = blockIdx.x * blockDim.x + threadIdx.x;
    if (gi < PW2_END) {
        const float* W; float *Wh, *Wl; int idx;
        if (gi < PW1_END) { W = W1; Wh = g_W1h; Wl = g_W1l; idx = gi; }
        else              { W = W2; Wh = g_W2h; Wl = g_W2l; idx = gi - PW1_END; }
        int n = idx / EV, k = idx % EV;
        float w = W[(size_t)k * EV + n];
        float hi = tf32_rn(w);
        Wh[idx] = hi; Wl[idx] = tf32_rn(w - hi);
    } else if (gi < PW3_END) {
        int idx = gi - PW2_END;
        int n = idx / EV, k = idx % EV;
        float w = (n < H3V) ? W3[(size_t)k * H3V + n] : 0.f;
        float hi = tf32_rn(w);
        g_W3h[idx] = hi; g_W3l[idx] = tf32_rn(w - hi);
    } else if (gi < PW4_END) {
        int idx = gi - PW3_END;
        int n = idx / H3P, k = idx % H3P;
        float w = (n < CV && k < H3V) ? W4[(size_t)k * CV + n] : 0.f;
        float hi = tf32_rn(w);
        g_W4h[idx] = hi; g_W4l[idx] = tf32_rn(w - hi);
    } else if (gi < PB3_END) {
        int i = gi - PW4_END;
        g_b3p[i] = (i < H3V) ? b3[i] : 0.f;
    } else if (gi < PB4_END) {
        int i = gi - PB3_END;
        g_b4p[i] = (i < CV) ? b4[i] : 0.f;
    }
}

#define GSTRIDE 36

// ---------------- GEMM A: BN=128, 2 CTAs/SM (R14 measured-best) ----------
// 32x64 warp tiles: wm = wid&3 (32-row band), wn = wid>>2 (64-col half).
#define A128_F   (128 * GSTRIDE)
#define B128_F   (128 * GSTRIDE)
#define STG128_F (A128_F + 2 * B128_F)
#define OFF128_A  0
#define OFF128_BH A128_F
#define OFF128_BL (A128_F + B128_F)
#define GT_SMEM_128 (2 * STG128_F * 4)     // 110592 bytes

__global__ void __launch_bounds__(256, 2) gemm_tc128_kernel(
    const float* __restrict__ A, const float* __restrict__ Bh,
    const float* __restrict__ Bl, const float* __restrict__ bias,
    float* __restrict__ C, int Kp, int Np, int lda, int ldc, int act)
{
    extern __shared__ float sm[];
    const int tid  = threadIdx.x;
    const int wid  = tid >> 5;
    const int lane = tid & 31;
    const int lr   = lane >> 2;
    const int lc   = lane & 3;
    const int wm   = wid & 3;
    const int wn   = wid >> 2;
    const int rowBase = blockIdx.y * 128;
    const int colBase = blockIdx.x * 128;
    const uint32_t sbase = (uint32_t)__cvta_generic_to_shared(sm);
    const int r0 = tid >> 3;
    const int q0 = tid & 7;

    float acc[2][8][4];
#pragma unroll
    for (int mt = 0; mt < 2; mt++)
#pragma unroll
        for (int nt = 0; nt < 8; nt++)
#pragma unroll
            for (int q = 0; q < 4; q++) acc[mt][nt][q] = 0.f;

    const int nchunks = Kp / 32;

#define STAGE128(s, kb) do {                                                  \
        uint32_t sb_ = sbase + (s) * (STG128_F * 4);                          \
        _Pragma("unroll")                                                     \
        for (int i_ = 0; i_ < 4; i_++) {                                      \
            int r_ = r0 + 32 * i_;                                            \
            uint32_t so_ = (uint32_t)((r_ * GSTRIDE + 4 * q0) * 4);           \
            CPA16(sb_ + OFF128_A * 4 + so_,                                   \
                  A + (size_t)(rowBase + r_) * lda + (kb) + 4 * q0);          \
            CPA16(sb_ + OFF128_BH * 4 + so_,                                  \
                  Bh + (size_t)(colBase + r_) * Kp + (kb) + 4 * q0);          \
            CPA16(sb_ + OFF128_BL * 4 + so_,                                  \
                  Bl + (size_t)(colBase + r_) * Kp + (kb) + 4 * q0);          \
        }                                                                     \
        CP_COMMIT;                                                            \
    } while (0)

    STAGE128(0, 0);

    for (int ch = 0; ch < nchunks; ch++) {
        if (ch + 1 < nchunks) {
            STAGE128((ch + 1) & 1, (ch + 1) * 32);
            CP_WAIT(1);
        } else {
            CP_WAIT(0);
        }
        __syncthreads();

        const float* sA  = sm + (ch & 1) * STG128_F + OFF128_A;
        const float* sBH = sm + (ch & 1) * STG128_F + OFF128_BH;
        const float* sBL = sm + (ch & 1) * STG128_F + OFF128_BL;

#pragma unroll
        for (int ks = 0; ks < 4; ks++) {
            const int k0 = ks * 8;
            unsigned aH[2][4], aL[2][4], bH[8][2], bL[8][2];
#pragma unroll
            for (int mt = 0; mt < 2; mt++) {
                int base = (wm * 32 + mt * 16 + lr) * GSTRIDE + k0 + lc;
                float r0v = sA[base];
                float r1v = sA[base + 8 * GSTRIDE];
                float r2v = sA[base + 4];
                float r3v = sA[base + 8 * GSTRIDE + 4];
                float h0 = tf32_rn(r0v), h1 = tf32_rn(r1v);
                float h2 = tf32_rn(r2v), h3 = tf32_rn(r3v);
                aH[mt][0] = __float_as_uint(h0);
                aH[mt][1] = __float_as_uint(h1);
                aH[mt][2] = __float_as_uint(h2);
                aH[mt][3] = __float_as_uint(h3);
                aL[mt][0] = __float_as_uint(tf32_rn(r0v - h0));
                aL[mt][1] = __float_as_uint(tf32_rn(r1v - h1));
                aL[mt][2] = __float_as_uint(tf32_rn(r2v - h2));
                aL[mt][3] = __float_as_uint(tf32_rn(r3v - h3));
            }
#pragma unroll
            for (int nt = 0; nt < 8; nt++) {
                int base = (wn * 64 + nt * 8 + lr) * GSTRIDE + k0 + lc;
                bH[nt][0] = __float_as_uint(sBH[base]);
                bH[nt][1] = __float_as_uint(sBH[base + 4]);
                bL[nt][0] = __float_as_uint(sBL[base]);
                bL[nt][1] = __float_as_uint(sBL[base + 4]);
            }
#pragma unroll
            for (int mt = 0; mt < 2; mt++)
#pragma unroll
                for (int nt = 0; nt < 8; nt++) {
                    MMA_TF32(acc[mt][nt], aL[mt], bH[nt]);
                    MMA_TF32(acc[mt][nt], aH[mt], bL[nt]);
                    MMA_TF32(acc[mt][nt], aH[mt], bH[nt]);
                }
        }
        __syncthreads();
    }
#undef STAGE128

#pragma unroll
    for (int mt = 0; mt < 2; mt++) {
        int row = rowBase + wm * 32 + mt * 16 + lr;
#pragma unroll
        for (int nt = 0; nt < 8; nt++) {
            int col = colBase + wn * 64 + nt * 8 + lc * 2;
            float v0 = acc[mt][nt][0] + bias[col];
            float v1 = acc[mt][nt][1] + bias[col + 1];
            float v2 = acc[mt][nt][2] + bias[col];
            float v3 = acc[mt][nt][3] + bias[col + 1];
            if (act) {
                v0 = (v0 >= 0.f) ? v0 : 0.01f * v0;
                v1 = (v1 >= 0.f) ? v1 : 0.01f * v1;
                v2 = (v2 >= 0.f) ? v2 : 0.01f * v2;
                v3 = (v3 >= 0.f) ? v3 : 0.01f * v3;
            }
            C[(size_t)row * ldc + col]           = v0;
            C[(size_t)row * ldc + col + 1]       = v1;
            C[(size_t)(row + 8) * ldc + col]     = v2;
            C[(size_t)(row + 8) * ldc + col + 1] = v3;
        }
    }
}

// ---------------- GEMM B: BN=64, 3 CTAs/SM (R15 variant, marginal best) --
#define BN64    64
#define A64_F   (128 * GSTRIDE)
#define B64_F   (BN64 * GSTRIDE)
#define STG64_F (A64_F + 2 * B64_F)
#define OFF64_A  0
#define OFF64_BH A64_F
#define OFF64_BL (A64_F + B64_F)
#define GT_SMEM_64 (2 * STG64_F * 4)       // 73728 bytes

__global__ void __launch_bounds__(256, 3) gemm_tc64_kernel(
    const float* __restrict__ A, const float* __restrict__ Bh,
    const float* __restrict__ Bl, const float* __restrict__ bias,
    float* __restrict__ C, int Kp, int Np, int lda, int ldc, int act)
{
    extern __shared__ float sm[];
    const int tid  = threadIdx.x;
    const int wid  = tid >> 5;
    const int lane = tid & 31;
    const int lr   = lane >> 2;
    const int lc   = lane & 3;
    const int wm   = wid & 3;
    const int wn   = wid >> 2;
    const int rowBase = blockIdx.y * 128;
    const int colBase = blockIdx.x * BN64;
    const uint32_t sbase = (uint32_t)__cvta_generic_to_shared(sm);
    const int r0 = tid >> 3;
    const int q0 = tid & 7;

    float acc[2][4][4];
#pragma unroll
    for (int mt = 0; mt < 2; mt++)
#pragma unroll
        for (int nt = 0; nt < 4; nt++)
#pragma unroll
            for (int q = 0; q < 4; q++) acc[mt][nt][q] = 0.f;

    const int nchunks = Kp / 32;

#define STAGE64(s, kb) do {                                                   \
        uint32_t sb_ = sbase + (s) * (STG64_F * 4);                           \
        _Pragma("unroll")                                                     \
        for (int i_ = 0; i_ < 4; i_++) {                                      \
            int r_ = r0 + 32 * i_;                                            \
            uint32_t so_ = (uint32_t)((r_ * GSTRIDE + 4 * q0) * 4);           \
            CPA16(sb_ + OFF64_A * 4 + so_,                                    \
                  A + (size_t)(rowBase + r_) * lda + (kb) + 4 * q0);          \
        }                                                                     \
        _Pragma("unroll")                                                     \
        for (int i_ = 0; i_ < 2; i_++) {                                      \
            int r_ = r0 + 32 * i_;                                            \
            uint32_t so_ = (uint32_t)((r_ * GSTRIDE + 4 * q0) * 4);           \
            CPA16(sb_ + OFF64_BH * 4 + so_,                                   \
                  Bh + (size_t)(colBase + r_) * Kp + (kb) + 4 * q0);          \
            CPA16(sb_ + OFF64_BL * 4 + so_,                                   \
                  Bl + (size_t)(colBase + r_) * Kp + (kb) + 4 * q0);          \
        }                                                                     \
        CP_COMMIT;                                                            \
    } while (0)

    STAGE64(0, 0);

    for (int ch = 0; ch < nchunks; ch++) {
        if (ch + 1 < nchunks) {
            STAGE64((ch + 1) & 1, (ch + 1) * 32);
            CP_WAIT(1);
        } else {
            CP_WAIT(0);
        }
        __syncthreads();

        const float* sA  = sm + (ch & 1) * STG64_F + OFF64_A;
        const float* sBH = sm + (ch & 1) * STG64_F + OFF64_BH;
        const float* sBL = sm + (ch & 1) * STG64_F + OFF64_BL;

#pragma unroll
        for (int ks = 0; ks < 4; ks++) {
            const int k0 = ks * 8;
            unsigned aH[2][4], aL[2][4];
#pragma unroll
            for (int mt = 0; mt < 2; mt++) {
                int base = (wm * 32 + mt * 16 + lr) * GSTRIDE + k0 + lc;
                float r0v = sA[base];
                float r1v = sA[base + 8 * GSTRIDE];
                float r2v = sA[base + 4];
                float r3v = sA[base + 8 * GSTRIDE + 4];
                float h0 = tf32_rn(r0v), h1 = tf32_rn(r1v);
                float h2 = tf32_rn(r2v), h3 = tf32_rn(r3v);
                aH[mt][0] = __float_as_uint(h0);
                aH[mt][1] = __float_as_uint(h1);
                aH[mt][2] = __float_as_uint(h2);
                aH[mt][3] = __float_as_uint(h3);
                aL[mt][0] = __float_as_uint(tf32_rn(r0v - h0));
                aL[mt][1] = __float_as_uint(tf32_rn(r1v - h1));
                aL[mt][2] = __float_as_uint(tf32_rn(r2v - h2));
                aL[mt][3] = __float_as_uint(tf32_rn(r3v - h3));
            }
#pragma unroll
            for (int nt = 0; nt < 4; nt++) {
                int base = (wn * 32 + nt * 8 + lr) * GSTRIDE + k0 + lc;
                unsigned bh[2], bl[2];
                bh[0] = __float_as_uint(sBH[base]);
                bh[1] = __float_as_uint(sBH[base + 4]);
                bl[0] = __float_as_uint(sBL[base]);
                bl[1] = __float_as_uint(sBL[base + 4]);
#pragma unroll
                for (int mt = 0; mt < 2; mt++) {
                    MMA_TF32(acc[mt][nt], aL[mt], bh);
                    MMA_TF32(acc[mt][nt], aH[mt], bl);
                    MMA_TF32(acc[mt][nt], aH[mt], bh);
                }
            }
        }
        __syncthreads();
    }
#undef STAGE64

#pragma unroll
    for (int mt = 0; mt < 2; mt++) {
        int row = rowBase + wm * 32 + mt * 16 + lr;
#pragma unroll
        for (int nt = 0; nt < 4; nt++) {
            int col = colBase + wn * 32 + nt * 8 + lc * 2;
            float v0 = acc[mt][nt][0] + bias[col];
            float v1 = acc[mt][nt][1] + bias[col + 1];
            float v2 = acc[mt][nt][2] + bias[col];
            float v3 = acc[mt][nt][3] + bias[col + 1];
            if (act) {
                v0 = (v0 >= 0.f) ? v0 : 0.01f * v0;
                v1 = (v1 >= 0.f) ? v1 : 0.01f * v1;
                v2 = (v2 >= 0.f) ? v2 : 0.01f * v2;
                v3 = (v3 >= 0.f) ? v3 : 0.01f * v3;
            }
            C[(size_t)row * ldc + col]           = v0;
            C[(size_t)row * ldc + col + 1]       = v1;
            C[(size_t)(row + 8) * ldc + col]     = v2;
            C[(size_t)(row + 8) * ldc + col + 1] = v3;
        }
    }
}

// ---------------- fused gumbel + pos/init (ONE launch) -------------------
__global__ void gumbel_pos_kernel(const int* __restrict__ vorder)
{
    const int total = (NV - 1) * CV;
    int i = blockIdx.x * blockDim.x + threadIdx.x;
    if (i < NV) {
        g_pos[vorder[i]] = i;
        g_colors[i] = -1;
    }
    if (i == 0) { g_viol = 0; g_next = 1; }
    if (i >= total) return;
    unsigned x0 = 0u;
    unsigned x1 = (unsigned)i;
    const unsigned k0 = 0u, k1 = 42u, k2 = 0u ^ 42u ^ 0x1BD11BDAu;
    x0 += k0; x1 += k1;
#define TFR(r) { x0 += x1; x1 = rotl32(x1, r); x1 ^= x0; }
    TFR(13) TFR(15) TFR(26) TFR(6)  x0 += k1; x1 += k2 + 1u;
    TFR(17) TFR(29) TFR(16) TFR(24) x0 += k2; x1 += k0 + 2u;
    TFR(13) TFR(15) TFR(26) TFR(6)  x0 += k0; x1 += k1 + 3u;
    TFR(17) TFR(29) TFR(16) TFR(24) x0 += k1; x1 += k2 + 4u;
    TFR(13) TFR(15) TFR(26) TFR(6)  x0 += k2; x1 += k0 + 5u;
#undef TFR
    unsigned bits = x0 ^ x1;
    unsigned fb = (bits >> 9) | 0x3f800000u;
    float f = __uint_as_float(fb) - 1.0f;
    const float tiny = 1.17549435e-38f;
    float u = fmaxf(tiny, f + tiny);
    g_gumbel[i] = -logf(-logf(u));
}

// ---------------- wavefront dataflow scan (dynamic assignment) -----------
#define SCAN_BLOCKS 296
#define SCAN_TPB    512

__global__ void __launch_bounds__(SCAN_TPB, 2) wavescan_kernel(
    const int* __restrict__ vorder, const int* __restrict__ adj)
{
    const int lane = threadIdx.x & 31;
    volatile int* vcol = g_colors;

    if (blockIdx.x == 0 && threadIdx.x == 0) {
        vcol[vorder[0]] = 0;               // first vertex -> color 0
    }

    const int c1 = lane + 32;
    const bool ok1 = (c1 < CV);
    const float NEGINF = __int_as_float((int)0xff800000);

    for (;;) {
        int t;
        if (lane == 0) t = atomicAdd(&g_next, 1);
        t = __shfl_sync(FULLM, t, 0);
        if (t >= NV) break;

        int v  = vorder[t];
        int nb = adj[v * DV + lane];
        int pn = g_pos[nb];
        float l0 = g_logits[v * LDL + lane];
        float l1 = ok1 ? g_logits[v * LDL + c1] : 0.f;
        float g0 = g_gumbel[(t - 1) * CV + lane];
        float g1 = ok1 ? g_gumbel[(t - 1) * CV + c1] : 0.f;

        bool need = (pn < t);
        int cn = -1;
        while (__any_sync(FULLM, need && cn < 0)) {
            if (need && cn < 0) cn = vcol[nb];
        }

        unsigned lo = 0u, hi = 0u;
        if (need) {
            if (cn < 32) lo = 1u << cn; else hi = 1u << (cn - 32);
        }
        lo = __reduce_or_sync(FULLM, lo);
        hi = __reduce_or_sync(FULLM, hi);

        bool m0 = (lo >> lane) & 1u;
        bool m1 = (!ok1) || ((hi >> lane) & 1u);
        float s0 = m0 ? NEGINF : (l0 + g0);
        float s1 = m1 ? NEGINF : (l1 + g1);
        float s; int idx;
        if (s1 > s0) { s = s1; idx = c1; } else { s = s0; idx = lane; }
        unsigned e = fenc(s);
        unsigned m = __reduce_max_sync(FULLM, e);
        unsigned ic = (e == m) ? (unsigned)idx : 64u;
        int chosen = (int)__reduce_min_sync(FULLM, ic);

        if (lane == 0) vcol[v] = chosen;   // publish ASAP

        // ---- logp term (off critical path) ----
        float mx = fmaxf(m0 ? NEGINF : l0, m1 ? NEGINF : l1);
        mx = fdec(__reduce_max_sync(FULLM, fenc(mx)));
        float ex = (m0 ? 0.f : expf(l0 - mx)) + (m1 ? 0.f : expf(l1 - mx));
#pragma unroll
        for (int o = 16; o; o >>= 1) ex += __shfl_xor_sync(FULLM, ex, o);
        float la = __shfl_sync(FULLM, l0, chosen & 31);
        float lb = __shfl_sync(FULLM, l1, chosen & 31);
        if (lane == 0) {
            float lc = (chosen < 32) ? la : lb;
            float prob = expf(lc - mx) / ex;
            g_terms[t] = logf(prob + 1e-8f) + 18.420680743952367f;
        }
    }
}

// ---------------- fused violation count + colors output ------------------
__global__ void viol_out_kernel(const int* __restrict__ adj,
                                float* __restrict__ out, int do_colors)
{
    int i = blockIdx.x * blockDim.x + threadIdx.x;
    int c = 0;
    if (i < NV * DV) {
        int n = i >> 5;            // DV == 32
        c = (g_colors[adj[i]] == g_colors[n]) ? 1 : 0;
    }
    c = __reduce_add_sync(FULLM, c);
    if ((threadIdx.x & 31) == 0 && c) atomicAdd(&g_viol, c);
    if (do_colors && i < NV) out[i] = (float)g_colors[i];
}

// ---------------- final reduction ----------------
__global__ void final_kernel(float* out, int mode)
{
    const int tid = threadIdx.x;
    float s = 0.f;
    for (int t = 1 + tid; t < NV; t += 1024) s += g_terms[t];
    unsigned long long um = 0ull;
    for (int i = tid; i < NV; i += 1024) um |= (1ull << (g_colors[i] & 63));
#pragma unroll
    for (int o = 16; o; o >>= 1) {
        s  += __shfl_xor_sync(FULLM, s, o);
        um |= __shfl_xor_sync(FULLM, um, o);
    }
    __shared__ float ws[32];
    __shared__ unsigned long long wm[32];
    int w = tid >> 5, l = tid & 31;
    if (l == 0) { ws[w] = s; wm[w] = um; }
    __syncthreads();
    if (tid == 0) {
        float tot = 0.f; unsigned long long m = 0ull;
        for (int i = 0; i < 32; i++) { tot += ws[i]; m |= wm[i]; }
        float confidence = tot / (float)NV;
        int nused = __popcll(m);
        float ratio = (float)g_viol / (float)(NV * DV);
        float cost = (float)nused + ratio * 100.0f;
        float loss = cost * confidence;
        if (mode == 0) out[NV] = loss;
        else           out[0]  = loss;
    }
}

// ---------------- host ----------------
extern "C" void kernel_launch(void* const* d_in, const int* in_sizes, int n_in,
                              void* d_out, int out_size)
{
    const float *emb = 0, *W1 = 0, *b1 = 0, *W2 = 0, *b2 = 0,
                *W3 = 0, *b3 = 0, *W4 = 0, *b4 = 0;
    const int *adj = 0, *vorder = 0;
    for (int i = 0; i < n_in; i++) {
        long s = in_sizes[i];
        void* p = d_in[i];
        if      (s == (long)NV * EV)  emb = (const float*)p;
        else if (s == (long)NV * DV)  adj = (const int*)p;
        else if (s == NV)             vorder = (const int*)p;
        else if (s == (long)EV * EV)  { if (!W1) W1 = (const float*)p; else W2 = (const float*)p; }
        else if (s == EV)             { if (!b1) b1 = (const float*)p; else b2 = (const float*)p; }
        else if (s == (long)EV * H3V) W3 = (const float*)p;
        else if (s == H3V)            b3 = (const float*)p;
        else if (s == (long)H3V * CV) W4 = (const float*)p;
        else if (s == CV)             b4 = (const float*)p;
    }
    if (!emb || !adj || !vorder || !W1 || !b1 || !W2 || !b2 || !W3 || !b3 || !W4 || !b4)
        return;

    float *h1, *h2, *logits;
    float *w1h, *w1l, *w2h, *w2l, *w3h, *w3l, *w4h, *w4l, *b3p, *b4p;
    cudaGetSymbolAddress((void**)&h1, g_bufA);
    cudaGetSymbolAddress((void**)&h2, g_bufB);
    cudaGetSymbolAddress((void**)&logits, g_logits);
    cudaGetSymbolAddress((void**)&w1h, g_W1h); cudaGetSymbolAddress((void**)&w1l, g_W1l);
    cudaGetSymbolAddress((void**)&w2h, g_W2h); cudaGetSymbolAddress((void**)&w2l, g_W2l);
    cudaGetSymbolAddress((void**)&w3h, g_W3h); cudaGetSymbolAddress((void**)&w3l, g_W3l);
    cudaGetSymbolAddress((void**)&w4h, g_W4h); cudaGetSymbolAddress((void**)&w4l, g_W4l);
    cudaGetSymbolAddress((void**)&b3p, g_b3p); cudaGetSymbolAddress((void**)&b4p, g_b4p);

    cudaFuncSetAttribute(gemm_tc128_kernel,
                         cudaFuncAttributeMaxDynamicSharedMemorySize, GT_SMEM_128);
    cudaFuncSetAttribute(gemm_tc64_kernel,
                         cudaFuncAttributeMaxDynamicSharedMemorySize, GT_SMEM_64);

    // fused weight prep (launch index 0)
    prep_all_kernel<<<(PB4_END + 255) / 256, 256>>>(W1, W2, W3, W4, b3, b4);

    // MLP GEMMs (index 3 = gemm3 gets profiled)
    gemm_tc128_kernel<<<dim3(EV / 128, NV / 128), 256, GT_SMEM_128>>>(
        emb, w1h, w1l, b1, h1, EV, EV, EV, EV, 1);
    gemm_tc128_kernel<<<dim3(EV / 128, NV / 128), 256, GT_SMEM_128>>>(
        h1, w2h, w2l, b2, h2, EV, EV, EV, EV, 1);
    gemm_tc64_kernel<<<dim3(H3P / 64, NV / 128), 256, GT_SMEM_64>>>(
        h2, w3h, w3l, b3p, h1, EV, H3P, EV, H3P, 1);
    gemm_tc64_kernel<<<dim3(LDL / 64, NV / 128), 256, GT_SMEM_64>>>(
        h1, w4h, w4l, b4p, logits, H3P, LDL, H3P, LDL, 0);

    gumbel_pos_kernel<<<((NV - 1) * CV + 255) / 256, 256>>>(vorder);

    wavescan_kernel<<<SCAN_BLOCKS, SCAN_TPB>>>(vorder, adj);

    float* outF = (float*)d_out;
    int do_colors = (out_size >= NV) ? 1 : 0;
    viol_out_kernel<<<(NV * DV + 255) / 256, 256>>>(adj, outF, do_colors);

    int mode = (out_size >= NV + 1) ? 0 : ((out_size < NV) ? 1 : 2);
    if (mode != 2)
        final_kernel<<<1, 1024>>>(outF, mode);
}